// round 15
// baseline (speedup 1.0000x reference)
#include <cuda_runtime.h>
#include <cuda_bf16.h>
#include <mma.h>
#include <cstdint>

using namespace nvcuda;

// ---------------------------------------------------------------------------
// FSRGraphConv round 15: R14 + BM=64 GEMM (3 blocks/SM, finer tiles).
//   stream 1: hist -> scan -> bucket -> aggregate -> [join] -> gemm
//   stream 2: prep_wc -> prep_B -> hconv
// ---------------------------------------------------------------------------

#define IN_F   128
#define E_F    32
#define FEAT   160
#define OUT_F  128
#define KTOT   288
#define MAX_NODES 50000
#define NPAD   50048
#define MAX_EDGES 800000
#define XLD    288

__device__ int  g_cnt[MAX_NODES];
__device__ int  g_off[MAX_NODES + 1];
__device__ int  g_cur[MAX_NODES];
__device__ int  g_bsum[256];
__device__ int  g_sync1;
__device__ int  g_sync2;
__device__ __align__(8) int2 g_pairs[MAX_EDGES];
__device__ __align__(16) float g_Wc[FEAT * OUT_F];
__device__ __align__(16) __nv_bfloat16 g_Xhi[(size_t)NPAD * XLD];
__device__ __align__(16) __nv_bfloat16 g_Xlo[(size_t)NPAD * XLD];
__device__ __align__(16) __nv_bfloat16 g_Bhi[KTOT * OUT_F];
__device__ __align__(16) __nv_bfloat16 g_Blo[KTOT * OUT_F];
__device__ __align__(16) float g_bvt[16 * OUT_F];

// ========================= bf16 split helpers ===============================
__device__ __forceinline__ uint32_t pk_bf2(__nv_bfloat16 a, __nv_bfloat16 b) {
    return (uint32_t)__bfloat16_as_ushort(a) |
           ((uint32_t)__bfloat16_as_ushort(b) << 16);
}
__device__ __forceinline__ void split4(float4 v, uint2& hi, uint2& lo) {
    __nv_bfloat16 h0 = __float2bfloat16(v.x);
    __nv_bfloat16 h1 = __float2bfloat16(v.y);
    __nv_bfloat16 h2 = __float2bfloat16(v.z);
    __nv_bfloat16 h3 = __float2bfloat16(v.w);
    __nv_bfloat16 l0 = __float2bfloat16(v.x - __bfloat162float(h0));
    __nv_bfloat16 l1 = __float2bfloat16(v.y - __bfloat162float(h1));
    __nv_bfloat16 l2 = __float2bfloat16(v.z - __bfloat162float(h2));
    __nv_bfloat16 l3 = __float2bfloat16(v.w - __bfloat162float(h3));
    hi = make_uint2(pk_bf2(h0, h1), pk_bf2(h2, h3));
    lo = make_uint2(pk_bf2(l0, l1), pk_bf2(l2, l3));
}

// ===================== stream 2: weight prep + hconv ========================
__global__ void prep_wc_kernel(const float* __restrict__ weight,
                               const float* __restrict__ W_w) {
    __shared__ float wrow[OUT_F];
    int k = blockIdx.x, o = threadIdx.x;
    wrow[o] = weight[k * OUT_F + o];
    __syncthreads();
    const float* wr = W_w + (size_t)o * (IN_F + OUT_F) + IN_F;
    float s = 0.f;
#pragma unroll 4
    for (int c = 0; c < OUT_F; c++) s = fmaf(wrow[c], wr[c], s);
    g_Wc[k * OUT_F + o] = s;
}

__global__ void prep_B_kernel(const float* __restrict__ W_w,
                              const float* __restrict__ W_b,
                              const float* __restrict__ bias) {
    int k = blockIdx.x;      // 0..287
    int n = threadIdx.x;     // 0..127
    float w = (k < IN_F) ? W_w[(size_t)n * (IN_F + OUT_F) + k]
                         : g_Wc[(size_t)(k - IN_F) * OUT_F + n];
    __nv_bfloat16 hi = __float2bfloat16(w);
    __nv_bfloat16 lo = __float2bfloat16(w - __bfloat162float(hi));
    g_Bhi[(size_t)k * OUT_F + n] = hi;
    g_Blo[(size_t)k * OUT_F + n] = lo;
    if (k < 16) g_bvt[k * OUT_F + n] = W_b[n] + bias[n];
}

__global__ void hconv_kernel(const float* __restrict__ h, int n_nodes) {
    int gid  = blockIdx.x * 256 + threadIdx.x;
    int node = gid >> 5;
    int lane = gid & 31;
    if (node >= n_nodes) return;
    float4 v = __ldg(reinterpret_cast<const float4*>(h + (size_t)node * IN_F) + lane);
    uint2 hi, lo;
    split4(v, hi, lo);
    size_t e = (size_t)node * XLD + lane * 4;
    *reinterpret_cast<uint2*>(g_Xhi + e) = hi;
    *reinterpret_cast<uint2*>(g_Xlo + e) = lo;
}

// ===================== stream 1: edge pipeline ==============================
__global__ void hist_kernel(const int* __restrict__ dst_idx, int n_edges) {
    int i = blockIdx.x * 256 + threadIdx.x;
    if (i < n_edges) atomicAdd(&g_cnt[dst_idx[i]], 1);
}

#define SCAN_BLOCKS 128
__global__ void scan_fused_kernel(int n) {
    __shared__ int ss[256];
    int t = threadIdx.x;
    int ntiles = (n + 255) >> 8;

    for (int tile = blockIdx.x; tile < ntiles; tile += SCAN_BLOCKS) {
        int i = tile * 256 + t;
        int c = (i < n) ? g_cnt[i] : 0;
        ss[t] = c; __syncthreads();
        for (int off = 1; off < 256; off <<= 1) {
            int v = (t >= off) ? ss[t - off] : 0;
            __syncthreads();
            ss[t] += v;
            __syncthreads();
        }
        if (i < n) g_off[i] = ss[t] - c;
        if (t == 255) g_bsum[tile] = ss[255];
        __syncthreads();
    }

    __threadfence();
    if (t == 0) atomicAdd(&g_sync1, 1);
    if (blockIdx.x == 0) {
        if (t == 0) while (atomicAdd(&g_sync1, 0) < SCAN_BLOCKS) __nanosleep(64);
        __syncthreads();
        int v = (t < ntiles) ? g_bsum[t] : 0;
        ss[t] = v; __syncthreads();
        for (int off = 1; off < 256; off <<= 1) {
            int x = (t >= off) ? ss[t - off] : 0;
            __syncthreads();
            ss[t] += x;
            __syncthreads();
        }
        if (t < ntiles) g_bsum[t] = ss[t] - v;
        if (t == 255) g_off[n] = ss[255];
        __threadfence();
        __syncthreads();
        if (t == 0) atomicAdd(&g_sync2, 1);
    } else {
        if (t == 0) while (atomicAdd(&g_sync2, 0) == 0) __nanosleep(64);
        __syncthreads();
    }

    // phase 2: finalize offsets AND zero g_cnt for the next replay
    for (int tile = blockIdx.x; tile < ntiles; tile += SCAN_BLOCKS) {
        int i = tile * 256 + t;
        if (i < n) {
            int o = g_off[i] + g_bsum[tile];
            g_off[i] = o;
            g_cur[i] = o;
            g_cnt[i] = 0;
        }
    }
}

__global__ void bucket_kernel(const int* __restrict__ src_idx,
                              const int* __restrict__ dst_idx,
                              int n_edges) {
    if (blockIdx.x == 0 && threadIdx.x == 0) { g_sync1 = 0; g_sync2 = 0; }
    int e = blockIdx.x * blockDim.x + threadIdx.x;
    if (e < n_edges) {
        int d = dst_idx[e];
        int pos = atomicAdd(&g_cur[d], 1);
        g_pairs[pos] = make_int2(src_idx[e], e);
    }
}

__global__ void aggregate_kernel(const float* __restrict__ h,
                                 const float* __restrict__ eftr,
                                 int n_nodes) {
    int lane = threadIdx.x & 31;
    int w    = (blockIdx.x * blockDim.x + threadIdx.x) >> 5;
    if (w >= n_nodes) return;

    int start = g_off[w];
    int end   = g_off[w + 1];
    int n     = end - start;

    float4 a0 = make_float4(0.f,0.f,0.f,0.f), a1 = a0, a2 = a0, a3 = a0;
    float  e0 = 0.f, e1 = 0.f, e2 = 0.f, e3 = 0.f;

    int j = start;
    for (; j + 3 < end; j += 4) {
        int2 c0 = g_pairs[j];
        int2 c1 = g_pairs[j + 1];
        int2 c2 = g_pairs[j + 2];
        int2 c3 = g_pairs[j + 3];
        float4 h0 = __ldg(reinterpret_cast<const float4*>(h + (size_t)c0.x * IN_F) + lane);
        float4 h1 = __ldg(reinterpret_cast<const float4*>(h + (size_t)c1.x * IN_F) + lane);
        float4 h2 = __ldg(reinterpret_cast<const float4*>(h + (size_t)c2.x * IN_F) + lane);
        float4 h3 = __ldg(reinterpret_cast<const float4*>(h + (size_t)c3.x * IN_F) + lane);
        float  v0 = __ldg(eftr + (size_t)c0.y * E_F + lane);
        float  v1 = __ldg(eftr + (size_t)c1.y * E_F + lane);
        float  v2 = __ldg(eftr + (size_t)c2.y * E_F + lane);
        float  v3 = __ldg(eftr + (size_t)c3.y * E_F + lane);
        a0.x += h0.x; a0.y += h0.y; a0.z += h0.z; a0.w += h0.w; e0 += v0;
        a1.x += h1.x; a1.y += h1.y; a1.z += h1.z; a1.w += h1.w; e1 += v1;
        a2.x += h2.x; a2.y += h2.y; a2.z += h2.z; a2.w += h2.w; e2 += v2;
        a3.x += h3.x; a3.y += h3.y; a3.z += h3.z; a3.w += h3.w; e3 += v3;
    }
    for (; j < end; j++) {
        int2 c0 = g_pairs[j];
        float4 h0 = __ldg(reinterpret_cast<const float4*>(h + (size_t)c0.x * IN_F) + lane);
        float  v0 = __ldg(eftr + (size_t)c0.y * E_F + lane);
        a0.x += h0.x; a0.y += h0.y; a0.z += h0.z; a0.w += h0.w; e0 += v0;
    }

    float inv = 1.f / (float)max(n, 1);
    float4 ah = make_float4((a0.x + a1.x + a2.x + a3.x) * inv,
                            (a0.y + a1.y + a2.y + a3.y) * inv,
                            (a0.z + a1.z + a2.z + a3.z) * inv,
                            (a0.w + a1.w + a2.w + a3.w) * inv);
    float  ae = (e0 + e1 + e2 + e3) * inv;

    uint2 hi, lo;
    split4(ah, hi, lo);
    size_t eh = (size_t)w * XLD + IN_F + lane * 4;
    *reinterpret_cast<uint2*>(g_Xhi + eh) = hi;
    *reinterpret_cast<uint2*>(g_Xlo + eh) = lo;

    __nv_bfloat16 ehi = __float2bfloat16(ae);
    __nv_bfloat16 elo = __float2bfloat16(ae - __bfloat162float(ehi));
    size_t ee = (size_t)w * XLD + 256 + lane;
    g_Xhi[ee] = ehi;
    g_Xlo[ee] = elo;
}

// ========================= cp.async WMMA GEMM (BM=64) =======================
#define BM 64
#define BN 128
#define BK 32
#define NKC 9
#define ALDM 56
#define BLDM 136
#define A_BYTES (BM * ALDM * 2)            // 7168
#define B_BYTES (BK * BLDM * 2)            // 8704
#define ST_ALO (A_BYTES)
#define ST_BHI (2 * A_BYTES)
#define ST_BLO (2 * A_BYTES + B_BYTES)
#define STAGE_BYTES (2 * A_BYTES + 2 * B_BYTES)   // 31744
#define SM_TOTAL (2 * STAGE_BYTES)                // 63488 (>= 32KB C staging)

__device__ __forceinline__ uint32_t smem_u32(const void* p) {
    return (uint32_t)__cvta_generic_to_shared(p);
}
__device__ __forceinline__ void cp16(uint32_t sdst, const void* gsrc) {
    asm volatile("cp.async.ca.shared.global [%0], [%1], 16;"
                 :: "r"(sdst), "l"(gsrc));
}

__global__ __launch_bounds__(256, 3) void gemm_wmma_kernel(
    float* __restrict__ out, int n_nodes)
{
    extern __shared__ __align__(16) char dsm[];
    float* Csm = reinterpret_cast<float*>(dsm);
    const uint32_t sb = smem_u32(dsm);

    int m0 = blockIdx.x * BM;
    int t  = threadIdx.x;
    int wid = t >> 5;
    int warpM = wid & 1;          // 2 M-tiles of 32 rows
    int warpN = wid >> 1;         // 4 N-tiles of 32 cols
    bool full_block = (m0 + BM) <= n_nodes;

    // A: 256 16B-units (64 rows x 4), 1 per thread
    int am0 = t >> 2, aq0 = t & 3;
    // B: 512 16B-units (32 rows x 16), 2 per thread
    int bk0 = t >> 4,          bq0 = t & 15;
    int bk1 = (t + 256) >> 4,  bq1 = (t + 256) & 15;

    const __nv_bfloat16* gA0h = g_Xhi + (size_t)(m0 + am0) * XLD + aq0 * 8;
    const __nv_bfloat16* gA0l = g_Xlo + (size_t)(m0 + am0) * XLD + aq0 * 8;
    const __nv_bfloat16* gB0h = g_Bhi + (size_t)bk0 * OUT_F + bq0 * 8;
    const __nv_bfloat16* gB0l = g_Blo + (size_t)bk0 * OUT_F + bq0 * 8;
    const __nv_bfloat16* gB1h = g_Bhi + (size_t)bk1 * OUT_F + bq1 * 8;
    const __nv_bfloat16* gB1l = g_Blo + (size_t)bk1 * OUT_F + bq1 * 8;

    uint32_t sA0 = sb + (am0 * ALDM + aq0 * 8) * 2;
    uint32_t sB0 = sb + ST_BHI + (bk0 * BLDM + bq0 * 8) * 2;
    uint32_t sB1 = sb + ST_BHI + (bk1 * BLDM + bq1 * 8) * 2;

    auto load_stage = [&](int kc, int buf) {
        uint32_t so = buf * STAGE_BYTES;
        int ko = kc * BK;
        cp16(sA0 + so,           gA0h + ko);
        cp16(sA0 + so + A_BYTES, gA0l + ko);
        size_t bo = (size_t)ko * OUT_F;
        cp16(sB0 + so,           gB0h + bo);
        cp16(sB0 + so + B_BYTES, gB0l + bo);
        cp16(sB1 + so,           gB1h + bo);
        cp16(sB1 + so + B_BYTES, gB1l + bo);
        asm volatile("cp.async.commit_group;");
    };

    wmma::fragment<wmma::accumulator, 16, 16, 16, float> c[2][2];
#pragma unroll
    for (int i = 0; i < 2; i++)
#pragma unroll
        for (int j = 0; j < 2; j++)
            wmma::load_matrix_sync(c[i][j], g_bvt + warpN * 32 + j * 16,
                                   OUT_F, wmma::mem_row_major);

    load_stage(0, 0);

    for (int kc = 0; kc < NKC; kc++) {
        if (kc + 1 < NKC) {
            load_stage(kc + 1, (kc + 1) & 1);
            asm volatile("cp.async.wait_group 1;");
        } else {
            asm volatile("cp.async.wait_group 0;");
        }
        __syncthreads();

        char* st = dsm + (kc & 1) * STAGE_BYTES;
        __nv_bfloat16* Ahi = reinterpret_cast<__nv_bfloat16*>(st);
        __nv_bfloat16* Alo = reinterpret_cast<__nv_bfloat16*>(st + ST_ALO);
        __nv_bfloat16* Bhi = reinterpret_cast<__nv_bfloat16*>(st + ST_BHI);
        __nv_bfloat16* Blo = reinterpret_cast<__nv_bfloat16*>(st + ST_BLO);

#pragma unroll
        for (int ks = 0; ks < 2; ks++) {
            wmma::fragment<wmma::matrix_a, 16, 16, 16, __nv_bfloat16, wmma::row_major> ah[2], al[2];
#pragma unroll
            for (int i = 0; i < 2; i++) {
                wmma::load_matrix_sync(ah[i], Ahi + (warpM * 32 + i * 16) * ALDM + ks * 16, ALDM);
                wmma::load_matrix_sync(al[i], Alo + (warpM * 32 + i * 16) * ALDM + ks * 16, ALDM);
            }
#pragma unroll
            for (int j = 0; j < 2; j++) {
                wmma::fragment<wmma::matrix_b, 16, 16, 16, __nv_bfloat16, wmma::row_major> wh, wl;
                wmma::load_matrix_sync(wh, Bhi + (ks * 16) * BLDM + warpN * 32 + j * 16, BLDM);
                wmma::load_matrix_sync(wl, Blo + (ks * 16) * BLDM + warpN * 32 + j * 16, BLDM);
#pragma unroll
                for (int i = 0; i < 2; i++) {
                    wmma::mma_sync(c[i][j], ah[i], wh, c[i][j]);
                    wmma::mma_sync(c[i][j], ah[i], wl, c[i][j]);
                    wmma::mma_sync(c[i][j], al[i], wh, c[i][j]);
                }
            }
        }
        __syncthreads();
    }

    if (full_block) {
#pragma unroll
        for (int i = 0; i < 2; i++)
#pragma unroll
            for (int j = 0; j < 2; j++)
                wmma::store_matrix_sync(
                    out + (size_t)(m0 + warpM * 32 + i * 16) * OUT_F + warpN * 32 + j * 16,
                    c[i][j], OUT_F, wmma::mem_row_major);
    } else {
#pragma unroll
        for (int i = 0; i < 2; i++)
#pragma unroll
            for (int j = 0; j < 2; j++)
                wmma::store_matrix_sync(
                    Csm + (size_t)(warpM * 32 + i * 16) * BN + warpN * 32 + j * 16,
                    c[i][j], BN, wmma::mem_row_major);
        __syncthreads();
#pragma unroll
        for (int p = 0; p < 8; p++) {
            int idx = t + p * 256;      // 0..2047
            int row = idx >> 5;
            int c4  = idx & 31;
            int node = m0 + row;
            if (node < n_nodes) {
                *reinterpret_cast<float4*>(out + (size_t)node * OUT_F + c4 * 4) =
                    *reinterpret_cast<const float4*>(Csm + (size_t)row * BN + c4 * 4);
            }
        }
    }
}

// ---------------------------------------------------------------------------
extern "C" void kernel_launch(void* const* d_in, const int* in_sizes, int n_in,
                              void* d_out, int out_size) {
    const float* h      = (const float*)d_in[0];
    const float* eftr   = (const float*)d_in[1];
    const float* weight = (const float*)d_in[2];
    const float* W_w    = (const float*)d_in[3];
    const float* W_b    = (const float*)d_in[4];
    const float* bias   = (const float*)d_in[5];
    const int*   src    = (const int*)d_in[6];
    const int*   dst    = (const int*)d_in[7];
    float* out = (float*)d_out;

    int n_nodes = in_sizes[0] / IN_F;
    int n_edges = in_sizes[7];
    int nbh = (n_edges + 255) / 256;           // 3125
    int nhc = (n_nodes * 32 + 255) / 256;      // 6250
    int ngb = (n_nodes + BM - 1) / BM;         // 782

    static cudaStream_t s2;
    static cudaEvent_t evFork, evJoin;
    static bool init_done = false;
    if (!init_done) {
        cudaFuncSetAttribute(gemm_wmma_kernel,
                             cudaFuncAttributeMaxDynamicSharedMemorySize, SM_TOTAL);
        cudaStreamCreateWithFlags(&s2, cudaStreamNonBlocking);
        cudaEventCreateWithFlags(&evFork, cudaEventDisableTiming);
        cudaEventCreateWithFlags(&evJoin, cudaEventDisableTiming);
        init_done = true;
    }

    // fork
    cudaEventRecord(evFork, 0);
    cudaStreamWaitEvent(s2, evFork, 0);

    // stream 2: weight prep + h conversion
    prep_wc_kernel<<<FEAT, OUT_F, 0, s2>>>(weight, W_w);
    prep_B_kernel<<<KTOT, OUT_F, 0, s2>>>(W_w, W_b, bias);
    hconv_kernel<<<nhc, 256, 0, s2>>>(h, n_nodes);
    cudaEventRecord(evJoin, s2);

    // stream 1 (capture stream): edge pipeline
    hist_kernel<<<nbh, 256>>>(dst, n_edges);
    scan_fused_kernel<<<SCAN_BLOCKS, 256>>>(n_nodes);
    bucket_kernel<<<nbh, 256>>>(src, dst, n_edges);
    aggregate_kernel<<<(n_nodes * 32 + 255) / 256, 256>>>(h, eftr, n_nodes);

    // join: gemm needs both pipelines
    cudaStreamWaitEvent(0, evJoin, 0);
    gemm_wmma_kernel<<<ngb, 256, SM_TOTAL>>>(out, n_nodes);
}

// round 16
// speedup vs baseline: 1.0829x; 1.0829x over previous
#include <cuda_runtime.h>
#include <cuda_bf16.h>
#include <mma.h>
#include <cstdint>

using namespace nvcuda;

// ---------------------------------------------------------------------------
// FSRGraphConv round 16: R14 kernels (BM=128 GEMM) + M-range chunked overlap:
//   stream 1: hist -> scan -> bucket -> aggA -> aggB -> gemmB
//   stream 2: prep_wc -> prep_B -> hconv -> [wait aggA] -> gemmA
// gemmA (rows 0..25088) overlaps aggB; no duplicated epilogue work.
// ---------------------------------------------------------------------------

#define IN_F   128
#define E_F    32
#define FEAT   160
#define OUT_F  128
#define KTOT   288
#define MAX_NODES 50000
#define NPAD   50048
#define MAX_EDGES 800000
#define XLD    288
#define M_SPLIT 25088          // 196 * 128

__device__ int  g_cnt[MAX_NODES];
__device__ int  g_off[MAX_NODES + 1];
__device__ int  g_cur[MAX_NODES];
__device__ int  g_bsum[256];
__device__ int  g_sync1;
__device__ int  g_sync2;
__device__ __align__(8) int2 g_pairs[MAX_EDGES];
__device__ __align__(16) float g_Wc[FEAT * OUT_F];
__device__ __align__(16) __nv_bfloat16 g_Xhi[(size_t)NPAD * XLD];
__device__ __align__(16) __nv_bfloat16 g_Xlo[(size_t)NPAD * XLD];
__device__ __align__(16) __nv_bfloat16 g_Bhi[KTOT * OUT_F];
__device__ __align__(16) __nv_bfloat16 g_Blo[KTOT * OUT_F];
__device__ __align__(16) float g_bvt[16 * OUT_F];

// ========================= bf16 split helpers ===============================
__device__ __forceinline__ uint32_t pk_bf2(__nv_bfloat16 a, __nv_bfloat16 b) {
    return (uint32_t)__bfloat16_as_ushort(a) |
           ((uint32_t)__bfloat16_as_ushort(b) << 16);
}
__device__ __forceinline__ void split4(float4 v, uint2& hi, uint2& lo) {
    __nv_bfloat16 h0 = __float2bfloat16(v.x);
    __nv_bfloat16 h1 = __float2bfloat16(v.y);
    __nv_bfloat16 h2 = __float2bfloat16(v.z);
    __nv_bfloat16 h3 = __float2bfloat16(v.w);
    __nv_bfloat16 l0 = __float2bfloat16(v.x - __bfloat162float(h0));
    __nv_bfloat16 l1 = __float2bfloat16(v.y - __bfloat162float(h1));
    __nv_bfloat16 l2 = __float2bfloat16(v.z - __bfloat162float(h2));
    __nv_bfloat16 l3 = __float2bfloat16(v.w - __bfloat162float(h3));
    hi = make_uint2(pk_bf2(h0, h1), pk_bf2(h2, h3));
    lo = make_uint2(pk_bf2(l0, l1), pk_bf2(l2, l3));
}

// ===================== stream 2: weight prep + hconv ========================
__global__ void prep_wc_kernel(const float* __restrict__ weight,
                               const float* __restrict__ W_w) {
    __shared__ float wrow[OUT_F];
    int k = blockIdx.x, o = threadIdx.x;
    wrow[o] = weight[k * OUT_F + o];
    __syncthreads();
    const float* wr = W_w + (size_t)o * (IN_F + OUT_F) + IN_F;
    float s = 0.f;
#pragma unroll 4
    for (int c = 0; c < OUT_F; c++) s = fmaf(wrow[c], wr[c], s);
    g_Wc[k * OUT_F + o] = s;
}

__global__ void prep_B_kernel(const float* __restrict__ W_w,
                              const float* __restrict__ W_b,
                              const float* __restrict__ bias) {
    int k = blockIdx.x;      // 0..287
    int n = threadIdx.x;     // 0..127
    float w = (k < IN_F) ? W_w[(size_t)n * (IN_F + OUT_F) + k]
                         : g_Wc[(size_t)(k - IN_F) * OUT_F + n];
    __nv_bfloat16 hi = __float2bfloat16(w);
    __nv_bfloat16 lo = __float2bfloat16(w - __bfloat162float(hi));
    g_Bhi[(size_t)k * OUT_F + n] = hi;
    g_Blo[(size_t)k * OUT_F + n] = lo;
    if (k < 16) g_bvt[k * OUT_F + n] = W_b[n] + bias[n];
}

__global__ void hconv_kernel(const float* __restrict__ h, int n_nodes) {
    int gid  = blockIdx.x * 256 + threadIdx.x;
    int node = gid >> 5;
    int lane = gid & 31;
    if (node >= n_nodes) return;
    float4 v = __ldg(reinterpret_cast<const float4*>(h + (size_t)node * IN_F) + lane);
    uint2 hi, lo;
    split4(v, hi, lo);
    size_t e = (size_t)node * XLD + lane * 4;
    *reinterpret_cast<uint2*>(g_Xhi + e) = hi;
    *reinterpret_cast<uint2*>(g_Xlo + e) = lo;
}

// ===================== stream 1: edge pipeline ==============================
__global__ void hist_kernel(const int* __restrict__ dst_idx, int n_edges) {
    int i = blockIdx.x * 256 + threadIdx.x;
    if (i < n_edges) atomicAdd(&g_cnt[dst_idx[i]], 1);
}

#define SCAN_BLOCKS 128
__global__ void scan_fused_kernel(int n) {
    __shared__ int ss[256];
    int t = threadIdx.x;
    int ntiles = (n + 255) >> 8;

    for (int tile = blockIdx.x; tile < ntiles; tile += SCAN_BLOCKS) {
        int i = tile * 256 + t;
        int c = (i < n) ? g_cnt[i] : 0;
        ss[t] = c; __syncthreads();
        for (int off = 1; off < 256; off <<= 1) {
            int v = (t >= off) ? ss[t - off] : 0;
            __syncthreads();
            ss[t] += v;
            __syncthreads();
        }
        if (i < n) g_off[i] = ss[t] - c;
        if (t == 255) g_bsum[tile] = ss[255];
        __syncthreads();
    }

    __threadfence();
    if (t == 0) atomicAdd(&g_sync1, 1);
    if (blockIdx.x == 0) {
        if (t == 0) while (atomicAdd(&g_sync1, 0) < SCAN_BLOCKS) __nanosleep(64);
        __syncthreads();
        int v = (t < ntiles) ? g_bsum[t] : 0;
        ss[t] = v; __syncthreads();
        for (int off = 1; off < 256; off <<= 1) {
            int x = (t >= off) ? ss[t - off] : 0;
            __syncthreads();
            ss[t] += x;
            __syncthreads();
        }
        if (t < ntiles) g_bsum[t] = ss[t] - v;
        if (t == 255) g_off[n] = ss[255];
        __threadfence();
        __syncthreads();
        if (t == 0) atomicAdd(&g_sync2, 1);
    } else {
        if (t == 0) while (atomicAdd(&g_sync2, 0) == 0) __nanosleep(64);
        __syncthreads();
    }

    // phase 2: finalize offsets AND zero g_cnt for the next replay
    for (int tile = blockIdx.x; tile < ntiles; tile += SCAN_BLOCKS) {
        int i = tile * 256 + t;
        if (i < n) {
            int o = g_off[i] + g_bsum[tile];
            g_off[i] = o;
            g_cur[i] = o;
            g_cnt[i] = 0;
        }
    }
}

__global__ void bucket_kernel(const int* __restrict__ src_idx,
                              const int* __restrict__ dst_idx,
                              int n_edges) {
    if (blockIdx.x == 0 && threadIdx.x == 0) { g_sync1 = 0; g_sync2 = 0; }
    int e = blockIdx.x * blockDim.x + threadIdx.x;
    if (e < n_edges) {
        int d = dst_idx[e];
        int pos = atomicAdd(&g_cur[d], 1);
        g_pairs[pos] = make_int2(src_idx[e], e);
    }
}

// warp per dst in [w_base, w_end)
__global__ void aggregate_kernel(const float* __restrict__ h,
                                 const float* __restrict__ eftr,
                                 int w_base, int w_end) {
    int lane = threadIdx.x & 31;
    int w    = w_base + ((blockIdx.x * blockDim.x + threadIdx.x) >> 5);
    if (w >= w_end) return;

    int start = g_off[w];
    int end   = g_off[w + 1];
    int n     = end - start;

    float4 a0 = make_float4(0.f,0.f,0.f,0.f), a1 = a0, a2 = a0, a3 = a0;
    float  e0 = 0.f, e1 = 0.f, e2 = 0.f, e3 = 0.f;

    int j = start;
    for (; j + 3 < end; j += 4) {
        int2 c0 = g_pairs[j];
        int2 c1 = g_pairs[j + 1];
        int2 c2 = g_pairs[j + 2];
        int2 c3 = g_pairs[j + 3];
        float4 h0 = __ldg(reinterpret_cast<const float4*>(h + (size_t)c0.x * IN_F) + lane);
        float4 h1 = __ldg(reinterpret_cast<const float4*>(h + (size_t)c1.x * IN_F) + lane);
        float4 h2 = __ldg(reinterpret_cast<const float4*>(h + (size_t)c2.x * IN_F) + lane);
        float4 h3 = __ldg(reinterpret_cast<const float4*>(h + (size_t)c3.x * IN_F) + lane);
        float  v0 = __ldg(eftr + (size_t)c0.y * E_F + lane);
        float  v1 = __ldg(eftr + (size_t)c1.y * E_F + lane);
        float  v2 = __ldg(eftr + (size_t)c2.y * E_F + lane);
        float  v3 = __ldg(eftr + (size_t)c3.y * E_F + lane);
        a0.x += h0.x; a0.y += h0.y; a0.z += h0.z; a0.w += h0.w; e0 += v0;
        a1.x += h1.x; a1.y += h1.y; a1.z += h1.z; a1.w += h1.w; e1 += v1;
        a2.x += h2.x; a2.y += h2.y; a2.z += h2.z; a2.w += h2.w; e2 += v2;
        a3.x += h3.x; a3.y += h3.y; a3.z += h3.z; a3.w += h3.w; e3 += v3;
    }
    for (; j < end; j++) {
        int2 c0 = g_pairs[j];
        float4 h0 = __ldg(reinterpret_cast<const float4*>(h + (size_t)c0.x * IN_F) + lane);
        float  v0 = __ldg(eftr + (size_t)c0.y * E_F + lane);
        a0.x += h0.x; a0.y += h0.y; a0.z += h0.z; a0.w += h0.w; e0 += v0;
    }

    float inv = 1.f / (float)max(n, 1);
    float4 ah = make_float4((a0.x + a1.x + a2.x + a3.x) * inv,
                            (a0.y + a1.y + a2.y + a3.y) * inv,
                            (a0.z + a1.z + a2.z + a3.z) * inv,
                            (a0.w + a1.w + a2.w + a3.w) * inv);
    float  ae = (e0 + e1 + e2 + e3) * inv;

    uint2 hi, lo;
    split4(ah, hi, lo);
    size_t eh = (size_t)w * XLD + IN_F + lane * 4;
    *reinterpret_cast<uint2*>(g_Xhi + eh) = hi;
    *reinterpret_cast<uint2*>(g_Xlo + eh) = lo;

    __nv_bfloat16 ehi = __float2bfloat16(ae);
    __nv_bfloat16 elo = __float2bfloat16(ae - __bfloat162float(ehi));
    size_t ee = (size_t)w * XLD + 256 + lane;
    g_Xhi[ee] = ehi;
    g_Xlo[ee] = elo;
}

// ========================= cp.async WMMA GEMM (BM=128, R14) =================
#define BM 128
#define BN 128
#define BK 32
#define NKC 9
#define ALDM 56
#define BLDM 136
#define A_BYTES (BM * ALDM * 2)
#define B_BYTES (BK * BLDM * 2)
#define ST_ALO (A_BYTES)
#define ST_BHI (2 * A_BYTES)
#define ST_BLO (2 * A_BYTES + B_BYTES)
#define STAGE_BYTES (2 * A_BYTES + 2 * B_BYTES)   // 46080
#define SM_TOTAL (2 * STAGE_BYTES)                // 92160

__device__ __forceinline__ uint32_t smem_u32(const void* p) {
    return (uint32_t)__cvta_generic_to_shared(p);
}
__device__ __forceinline__ void cp16(uint32_t sdst, const void* gsrc) {
    asm volatile("cp.async.ca.shared.global [%0], [%1], 16;"
                 :: "r"(sdst), "l"(gsrc));
}

__global__ __launch_bounds__(256, 2) void gemm_wmma_kernel(
    float* __restrict__ out, int n_nodes, int m_base)
{
    extern __shared__ __align__(16) char dsm[];
    float* Csm = reinterpret_cast<float*>(dsm);
    const uint32_t sb = smem_u32(dsm);

    int m0 = m_base + blockIdx.x * BM;
    int t  = threadIdx.x;
    int wid = t >> 5;
    int warpM = wid & 3;
    int warpN = wid >> 2;
    bool full_block = (m0 + BM) <= n_nodes;

    int am0 = t >> 2,          aq0 = t & 3;
    int am1 = (t + 256) >> 2,  aq1 = (t + 256) & 3;
    int bk0 = t >> 4,          bq0 = t & 15;
    int bk1 = (t + 256) >> 4,  bq1 = (t + 256) & 15;

    const __nv_bfloat16* gA0h = g_Xhi + (size_t)(m0 + am0) * XLD + aq0 * 8;
    const __nv_bfloat16* gA0l = g_Xlo + (size_t)(m0 + am0) * XLD + aq0 * 8;
    const __nv_bfloat16* gA1h = g_Xhi + (size_t)(m0 + am1) * XLD + aq1 * 8;
    const __nv_bfloat16* gA1l = g_Xlo + (size_t)(m0 + am1) * XLD + aq1 * 8;
    const __nv_bfloat16* gB0h = g_Bhi + (size_t)bk0 * OUT_F + bq0 * 8;
    const __nv_bfloat16* gB0l = g_Blo + (size_t)bk0 * OUT_F + bq0 * 8;
    const __nv_bfloat16* gB1h = g_Bhi + (size_t)bk1 * OUT_F + bq1 * 8;
    const __nv_bfloat16* gB1l = g_Blo + (size_t)bk1 * OUT_F + bq1 * 8;

    uint32_t sA0 = sb + (am0 * ALDM + aq0 * 8) * 2;
    uint32_t sA1 = sb + (am1 * ALDM + aq1 * 8) * 2;
    uint32_t sB0 = sb + ST_BHI + (bk0 * BLDM + bq0 * 8) * 2;
    uint32_t sB1 = sb + ST_BHI + (bk1 * BLDM + bq1 * 8) * 2;

    auto load_stage = [&](int kc, int buf) {
        uint32_t so = buf * STAGE_BYTES;
        int ko = kc * BK;
        cp16(sA0 + so,           gA0h + ko);
        cp16(sA0 + so + A_BYTES, gA0l + ko);
        cp16(sA1 + so,           gA1h + ko);
        cp16(sA1 + so + A_BYTES, gA1l + ko);
        size_t bo = (size_t)ko * OUT_F;
        cp16(sB0 + so,           gB0h + bo);
        cp16(sB0 + so + B_BYTES, gB0l + bo);
        cp16(sB1 + so,           gB1h + bo);
        cp16(sB1 + so + B_BYTES, gB1l + bo);
        asm volatile("cp.async.commit_group;");
    };

    wmma::fragment<wmma::accumulator, 16, 16, 16, float> c[2][4];
#pragma unroll
    for (int i = 0; i < 2; i++)
#pragma unroll
        for (int j = 0; j < 4; j++)
            wmma::load_matrix_sync(c[i][j], g_bvt + warpN * 64 + j * 16,
                                   OUT_F, wmma::mem_row_major);

    load_stage(0, 0);

    for (int kc = 0; kc < NKC; kc++) {
        if (kc + 1 < NKC) {
            load_stage(kc + 1, (kc + 1) & 1);
            asm volatile("cp.async.wait_group 1;");
        } else {
            asm volatile("cp.async.wait_group 0;");
        }
        __syncthreads();

        char* st = dsm + (kc & 1) * STAGE_BYTES;
        __nv_bfloat16* Ahi = reinterpret_cast<__nv_bfloat16*>(st);
        __nv_bfloat16* Alo = reinterpret_cast<__nv_bfloat16*>(st + ST_ALO);
        __nv_bfloat16* Bhi = reinterpret_cast<__nv_bfloat16*>(st + ST_BHI);
        __nv_bfloat16* Blo = reinterpret_cast<__nv_bfloat16*>(st + ST_BLO);

#pragma unroll
        for (int ks = 0; ks < 2; ks++) {
            wmma::fragment<wmma::matrix_a, 16, 16, 16, __nv_bfloat16, wmma::row_major> ah[2], al[2];
#pragma unroll
            for (int i = 0; i < 2; i++) {
                wmma::load_matrix_sync(ah[i], Ahi + (warpM * 32 + i * 16) * ALDM + ks * 16, ALDM);
                wmma::load_matrix_sync(al[i], Alo + (warpM * 32 + i * 16) * ALDM + ks * 16, ALDM);
            }
#pragma unroll
            for (int j = 0; j < 4; j++) {
                wmma::fragment<wmma::matrix_b, 16, 16, 16, __nv_bfloat16, wmma::row_major> wh, wl;
                wmma::load_matrix_sync(wh, Bhi + (ks * 16) * BLDM + warpN * 64 + j * 16, BLDM);
                wmma::load_matrix_sync(wl, Blo + (ks * 16) * BLDM + warpN * 64 + j * 16, BLDM);
#pragma unroll
                for (int i = 0; i < 2; i++) {
                    wmma::mma_sync(c[i][j], ah[i], wh, c[i][j]);
                    wmma::mma_sync(c[i][j], ah[i], wl, c[i][j]);
                    wmma::mma_sync(c[i][j], al[i], wh, c[i][j]);
                }
            }
        }
        __syncthreads();
    }

    if (full_block) {
#pragma unroll
        for (int i = 0; i < 2; i++)
#pragma unroll
            for (int j = 0; j < 4; j++)
                wmma::store_matrix_sync(
                    out + (size_t)(m0 + warpM * 32 + i * 16) * OUT_F + warpN * 64 + j * 16,
                    c[i][j], OUT_F, wmma::mem_row_major);
    } else {
#pragma unroll
        for (int i = 0; i < 2; i++)
#pragma unroll
            for (int j = 0; j < 4; j++)
                wmma::store_matrix_sync(
                    Csm + (size_t)(warpM * 32 + i * 16) * BN + warpN * 64 + j * 16,
                    c[i][j], BN, wmma::mem_row_major);
        __syncthreads();
#pragma unroll
        for (int p = 0; p < 16; p++) {
            int idx = t + p * 256;
            int row = idx >> 5;
            int c4  = idx & 31;
            int node = m0 + row;
            if (node < n_nodes) {
                *reinterpret_cast<float4*>(out + (size_t)node * OUT_F + c4 * 4) =
                    *reinterpret_cast<const float4*>(Csm + (size_t)row * BN + c4 * 4);
            }
        }
    }
}

// ---------------------------------------------------------------------------
extern "C" void kernel_launch(void* const* d_in, const int* in_sizes, int n_in,
                              void* d_out, int out_size) {
    const float* h      = (const float*)d_in[0];
    const float* eftr   = (const float*)d_in[1];
    const float* weight = (const float*)d_in[2];
    const float* W_w    = (const float*)d_in[3];
    const float* W_b    = (const float*)d_in[4];
    const float* bias   = (const float*)d_in[5];
    const int*   src    = (const int*)d_in[6];
    const int*   dst    = (const int*)d_in[7];
    float* out = (float*)d_out;

    int n_nodes = in_sizes[0] / IN_F;
    int n_edges = in_sizes[7];
    int nbh = (n_edges + 255) / 256;           // 3125
    int nhc = (n_nodes * 32 + 255) / 256;      // 6250

    int nA  = (M_SPLIT < n_nodes) ? M_SPLIT : n_nodes;
    int ngA = nA / BM;                                    // 196 full blocks
    int ngB = (n_nodes - nA + BM - 1) / BM;               // 195 (ragged)

    static cudaStream_t s2;
    static cudaEvent_t evFork, evPrep, evA, evS2done;
    static bool init_done = false;
    if (!init_done) {
        cudaFuncSetAttribute(gemm_wmma_kernel,
                             cudaFuncAttributeMaxDynamicSharedMemorySize, SM_TOTAL);
        cudaStreamCreateWithFlags(&s2, cudaStreamNonBlocking);
        cudaEventCreateWithFlags(&evFork,   cudaEventDisableTiming);
        cudaEventCreateWithFlags(&evPrep,   cudaEventDisableTiming);
        cudaEventCreateWithFlags(&evA,      cudaEventDisableTiming);
        cudaEventCreateWithFlags(&evS2done, cudaEventDisableTiming);
        init_done = true;
    }

    // fork
    cudaEventRecord(evFork, 0);
    cudaStreamWaitEvent(s2, evFork, 0);

    // stream 2: weight prep + h conversion
    prep_wc_kernel<<<FEAT, OUT_F, 0, s2>>>(weight, W_w);
    prep_B_kernel<<<KTOT, OUT_F, 0, s2>>>(W_w, W_b, bias);
    hconv_kernel<<<nhc, 256, 0, s2>>>(h, n_nodes);
    cudaEventRecord(evPrep, s2);

    // stream 1 (capture): edge pipeline, aggregate split in two halves
    hist_kernel<<<nbh, 256>>>(dst, n_edges);
    scan_fused_kernel<<<SCAN_BLOCKS, 256>>>(n_nodes);
    bucket_kernel<<<nbh, 256>>>(src, dst, n_edges);
    aggregate_kernel<<<(nA * 32 + 255) / 256, 256>>>(h, eftr, 0, nA);
    cudaEventRecord(evA, 0);
    if (n_nodes > nA)
        aggregate_kernel<<<((n_nodes - nA) * 32 + 255) / 256, 256>>>(h, eftr, nA, n_nodes);

    // stream 2: gemmA on rows [0, nA) — overlaps aggregate half 2
    cudaStreamWaitEvent(s2, evA, 0);
    gemm_wmma_kernel<<<ngA, 256, SM_TOTAL, s2>>>(out, n_nodes, 0);
    cudaEventRecord(evS2done, s2);

    // stream 1: gemmB on rows [nA, n_nodes) (needs hconv/prep too)
    cudaStreamWaitEvent(0, evPrep, 0);
    if (ngB > 0)
        gemm_wmma_kernel<<<ngB, 256, SM_TOTAL>>>(out, n_nodes, nA);

    // join side stream back into capture stream
    cudaStreamWaitEvent(0, evS2done, 0);
}